// round 2
// baseline (speedup 1.0000x reference)
#include <cuda_runtime.h>
#include <math.h>

#define B_  4
#define S_  512
#define D_  768
#define H_  12
#define DH_ 64
#define SD_ 30
#define BS_ (B_*S_)   // 2048

// ---- scratch (device globals: no allocation allowed) ----
__device__ float g_q  [B_*H_*S_*DH_];          // (b,h,s,d), pre-scaled by 1/8
__device__ float g_k  [B_*H_*S_*DH_];
__device__ float g_v  [B_*H_*S_*DH_];
__device__ float g_qws[B_*H_*S_*SD_];          // q @ Wsk^T
__device__ float g_qb [B_*H_*S_];              // q . bsk
__device__ float g_attn[(size_t)B_*H_*S_*S_];  // scores -> attn (50 MB)
__device__ float g_ctxa[B_*H_*S_*DH_];         // attn @ v
__device__ float g_ast [B_*H_*S_*SD_];         // sum_k attn * structure
__device__ float g_ctx [BS_*D_];               // merged ctx, (b,s,h*64+d)

// ============================================================
// Generic 64x64 tile GEMM, M=2048 N=768 K=768: C = X@W + bias
// sel: 0->g_q (scatter,scale), 1->g_k, 2->g_v, 3: X=g_ctx, out=extout plain
// ============================================================
__global__ void gemm_kernel(const float* __restrict__ Xin,
                            const float* __restrict__ W,
                            const float* __restrict__ bias,
                            float* __restrict__ extout,
                            float scale, int sel)
{
    const float* X = (sel == 3) ? g_ctx : Xin;
    float* outp = (sel == 0) ? g_q : (sel == 1) ? g_k : (sel == 2) ? g_v : extout;

    __shared__ float As[16][68];
    __shared__ float Bs[16][68];
    const int t  = threadIdx.x;                 // 256 threads
    const int tx = t & 15, ty = t >> 4;
    const int m0 = blockIdx.y * 64, n0 = blockIdx.x * 64;
    const int lm  = t >> 2;                     // 0..63 (A row)
    const int lk4 = (t & 3) * 4;                // A k-offset
    const int bk  = t >> 4;                     // 0..15 (B row)
    const int bn4 = (t & 15) * 4;               // B n-offset
    float acc[4][4] = {};

    for (int k0 = 0; k0 < 768; k0 += 16) {
        float4 a = *(const float4*)(X + (size_t)(m0 + lm) * 768 + k0 + lk4);
        float4 b = *(const float4*)(W + (size_t)(k0 + bk) * 768 + n0 + bn4);
        __syncthreads();
        As[lk4 + 0][lm] = a.x;
        As[lk4 + 1][lm] = a.y;
        As[lk4 + 2][lm] = a.z;
        As[lk4 + 3][lm] = a.w;
        *(float4*)&Bs[bk][bn4] = b;
        __syncthreads();
        #pragma unroll
        for (int kk = 0; kk < 16; kk++) {
            float ra[4], rb[4];
            #pragma unroll
            for (int i = 0; i < 4; i++) ra[i] = As[kk][ty*4 + i];
            #pragma unroll
            for (int j = 0; j < 4; j++) rb[j] = Bs[kk][tx*4 + j];
            #pragma unroll
            for (int i = 0; i < 4; i++)
                #pragma unroll
                for (int j = 0; j < 4; j++)
                    acc[i][j] += ra[i] * rb[j];
        }
    }

    #pragma unroll
    for (int i = 0; i < 4; i++) {
        int m = m0 + ty*4 + i;
        #pragma unroll
        for (int j = 0; j < 4; j++) {
            int n = n0 + tx*4 + j;
            float v = (acc[i][j] + bias[n]) * scale;
            if (sel < 3) {  // scatter to (b,h,s,d)
                int b_ = m >> 9, s = m & 511, h = n >> 6, d = n & 63;
                outp[(((size_t)b_*H_ + h)*S_ + s)*DH_ + d] = v;
            } else {
                outp[(size_t)m*768 + n] = v;
            }
        }
    }
}

// ============================================================
// qws[row,c] = sum_d q[row,d]*Wsk[c,d];  qb[row] = q . bsk
// ============================================================
__global__ void qws_kernel(const float* __restrict__ Wsk, const float* __restrict__ bsk)
{
    int idx = blockIdx.x * 256 + threadIdx.x;   // over B*H*S*32
    int c = idx & 31, row = idx >> 5;
    if (row >= B_*H_*S_) return;
    const float* q = g_q + (size_t)row * DH_;
    if (c < SD_) {
        const float* w = Wsk + c * DH_;
        float s = 0.f;
        #pragma unroll
        for (int d = 0; d < DH_; d++) s += q[d] * w[d];
        g_qws[(size_t)row*SD_ + c] = s;
    } else if (c == 31) {
        float s = 0.f;
        #pragma unroll
        for (int d = 0; d < DH_; d++) s += q[d] * bsk[d];
        g_qb[row] = s;
    }
}

// ============================================================
// scores pre-pass: g_attn[b,h,q,k] = structure[b,q,k,:].qws[b,h,q,:] + qb
// structure read ONCE, reused across all 12 heads.
// ============================================================
__global__ void struct_score_kernel(const float* __restrict__ structure)
{
    int b = blockIdx.z, q = blockIdx.y;
    int k = blockIdx.x * 128 + threadIdx.x;
    __shared__ float qw[H_][SD_];
    __shared__ float qb[H_];
    int t = threadIdx.x;
    for (int i = t; i < H_*SD_; i += 128) {
        int h = i / SD_, c = i % SD_;
        qw[h][c] = g_qws[(((size_t)b*H_ + h)*S_ + q)*SD_ + c];
    }
    if (t < H_) qb[t] = g_qb[((size_t)b*H_ + t)*S_ + q];
    __syncthreads();

    const float* st = structure + ((size_t)(b*S_ + q)*S_ + k) * SD_;
    float sv[SD_];
    #pragma unroll
    for (int c = 0; c < SD_; c += 2) {
        float2 v = *(const float2*)(st + c);
        sv[c] = v.x; sv[c+1] = v.y;
    }
    #pragma unroll
    for (int h = 0; h < H_; h++) {
        float acc = qb[h];
        #pragma unroll
        for (int c = 0; c < SD_; c++) acc += sv[c] * qw[h][c];
        g_attn[(((size_t)b*H_ + h)*S_ + q)*S_ + k] = acc;   // ALPHA = 1
    }
}

// ============================================================
// QK^T: g_attn += Q@K^T per (b,h), then apply mask
// mask is a 32-bit word per element (int32 0/1 or float32 0.0/1.0):
// nonzero word == masked.
// ============================================================
__global__ void qk_gemm_kernel(const unsigned int* __restrict__ mask)
{
    int bh = blockIdx.z;
    int b = bh / H_;
    const float* Q  = g_q + (size_t)bh * S_ * DH_;
    const float* Km = g_k + (size_t)bh * S_ * DH_;
    int q0 = blockIdx.y * 64, k0 = blockIdx.x * 64;
    __shared__ float Qs[16][68], Ks[16][68];
    int t = threadIdx.x;
    int tx = t & 15, ty = t >> 4;
    int lr = t >> 2, lc4 = (t & 3) * 4;
    float acc[4][4] = {};

    for (int d0 = 0; d0 < 64; d0 += 16) {
        float4 a = *(const float4*)(Q  + (size_t)(q0 + lr)*64 + d0 + lc4);
        float4 c = *(const float4*)(Km + (size_t)(k0 + lr)*64 + d0 + lc4);
        __syncthreads();
        Qs[lc4+0][lr]=a.x; Qs[lc4+1][lr]=a.y; Qs[lc4+2][lr]=a.z; Qs[lc4+3][lr]=a.w;
        Ks[lc4+0][lr]=c.x; Ks[lc4+1][lr]=c.y; Ks[lc4+2][lr]=c.z; Ks[lc4+3][lr]=c.w;
        __syncthreads();
        #pragma unroll
        for (int kk = 0; kk < 16; kk++) {
            float ra[4], rb[4];
            #pragma unroll
            for (int i = 0; i < 4; i++) ra[i] = Qs[kk][ty*4 + i];
            #pragma unroll
            for (int j = 0; j < 4; j++) rb[j] = Ks[kk][tx*4 + j];
            #pragma unroll
            for (int i = 0; i < 4; i++)
                #pragma unroll
                for (int j = 0; j < 4; j++)
                    acc[i][j] += ra[i] * rb[j];
        }
    }

    #pragma unroll
    for (int i = 0; i < 4; i++) {
        int q = q0 + ty*4 + i;
        #pragma unroll
        for (int j = 0; j < 4; j++) {
            int kx = k0 + tx*4 + j;
            size_t idx = ((size_t)bh*S_ + q)*S_ + kx;
            float v = acc[i][j] + g_attn[idx];
            if (mask[((size_t)b*S_ + q)*S_ + kx] != 0u) v = -1e18f;
            g_attn[idx] = v;
        }
    }
}

// ============================================================
// row softmax over k (512); head 0 rows also written to top_attn output
// ============================================================
__global__ void softmax_kernel(float* __restrict__ top_out)
{
    int r = blockIdx.x;                       // over B*H*S rows
    float* row = g_attn + (size_t)r * S_;
    int t = threadIdx.x;                      // 128
    float4 v = *(float4*)(row + t*4);
    float mx = fmaxf(fmaxf(v.x, v.y), fmaxf(v.z, v.w));
    __shared__ float redm[4], reds[4];
    #pragma unroll
    for (int o = 16; o > 0; o >>= 1) mx = fmaxf(mx, __shfl_xor_sync(0xffffffffu, mx, o));
    if ((t & 31) == 0) redm[t >> 5] = mx;
    __syncthreads();
    mx = fmaxf(fmaxf(redm[0], redm[1]), fmaxf(redm[2], redm[3]));

    v.x = __expf(v.x - mx); v.y = __expf(v.y - mx);
    v.z = __expf(v.z - mx); v.w = __expf(v.w - mx);
    float s = v.x + v.y + v.z + v.w;
    #pragma unroll
    for (int o = 16; o > 0; o >>= 1) s += __shfl_xor_sync(0xffffffffu, s, o);
    if ((t & 31) == 0) reds[t >> 5] = s;
    __syncthreads();
    s = reds[0] + reds[1] + reds[2] + reds[3];
    float inv = 1.0f / s;
    v.x *= inv; v.y *= inv; v.z *= inv; v.w *= inv;
    *(float4*)(row + t*4) = v;

    int h = (r / S_) % H_;
    if (h == 0) {
        int b = r / (H_ * S_), q = r % S_;
        *(float4*)(top_out + ((size_t)b*S_ + q)*S_ + t*4) = v;
    }
}

// ============================================================
// attn @ V per (b,h) -> g_ctxa
// ============================================================
__global__ void av_gemm_kernel()
{
    int bh = blockIdx.y;
    const float* A = g_attn + (size_t)bh * S_ * S_;
    const float* V = g_v    + (size_t)bh * S_ * DH_;
    int q0 = blockIdx.x * 64;
    __shared__ float As[16][68], Vs[16][68];
    int t = threadIdx.x;
    int tx = t & 15, ty = t >> 4;
    int lr = t >> 2, lc4 = (t & 3) * 4;
    int bk = t >> 4, bn4 = (t & 15) * 4;
    float acc[4][4] = {};

    for (int k0 = 0; k0 < 512; k0 += 16) {
        float4 a = *(const float4*)(A + (size_t)(q0 + lr)*512 + k0 + lc4);
        float4 b = *(const float4*)(V + (size_t)(k0 + bk)*64 + bn4);
        __syncthreads();
        As[lc4+0][lr]=a.x; As[lc4+1][lr]=a.y; As[lc4+2][lr]=a.z; As[lc4+3][lr]=a.w;
        *(float4*)&Vs[bk][bn4] = b;
        __syncthreads();
        #pragma unroll
        for (int kk = 0; kk < 16; kk++) {
            float ra[4], rb[4];
            #pragma unroll
            for (int i = 0; i < 4; i++) ra[i] = As[kk][ty*4 + i];
            #pragma unroll
            for (int j = 0; j < 4; j++) rb[j] = Vs[kk][tx*4 + j];
            #pragma unroll
            for (int i = 0; i < 4; i++)
                #pragma unroll
                for (int j = 0; j < 4; j++)
                    acc[i][j] += ra[i] * rb[j];
        }
    }
    #pragma unroll
    for (int i = 0; i < 4; i++)
        #pragma unroll
        for (int j = 0; j < 4; j++)
            g_ctxa[((size_t)bh*S_ + q0 + ty*4 + i)*DH_ + tx*4 + j] = acc[i][j];
}

// ============================================================
// g_ast[b,h,q,c] = sum_k attn[b,h,q,k] * structure[b,q,k,c]
// block: (b, 8 q-rows); thread owns (q, 4 heads, 6 c's)
// ============================================================
__global__ void ast_kernel(const float* __restrict__ structure)
{
    int b = blockIdx.y, q0 = blockIdx.x * 8;
    __shared__ float sA[8][12][33];
    __shared__ float sS[32][8][33];
    int t = threadIdx.x;                      // 128 (120 active)
    bool active = t < 120;
    int qq = 0, h0 = 0, c0 = 0;
    if (active) { qq = t / 15; int g = t % 15; h0 = (g / 5) * 4; c0 = (g % 5) * 6; }
    float acc[4][6] = {};

    for (int k0 = 0; k0 < 512; k0 += 32) {
        __syncthreads();
        for (int i = t; i < 8*12*32; i += 128) {
            int iq = i / 384; int r = i % 384; int ih = r >> 5; int ik = r & 31;
            sA[iq][ih][ik] = g_attn[(((size_t)b*H_ + ih)*S_ + q0 + iq)*S_ + k0 + ik];
        }
        for (int i = t; i < 8*32*30; i += 128) {
            int iq = i / 960; int r = i % 960; int ik = r / 30; int c = r % 30;
            sS[ik][iq][c] = structure[((size_t)(b*S_ + q0 + iq)*S_ + k0 + ik)*SD_ + c];
        }
        __syncthreads();
        if (active) {
            #pragma unroll 4
            for (int kk = 0; kk < 32; kk++) {
                float av[4], sv[6];
                #pragma unroll
                for (int i = 0; i < 4; i++) av[i] = sA[qq][h0 + i][kk];
                #pragma unroll
                for (int j = 0; j < 6; j++) sv[j] = sS[kk][qq][c0 + j];
                #pragma unroll
                for (int i = 0; i < 4; i++)
                    #pragma unroll
                    for (int j = 0; j < 6; j++)
                        acc[i][j] += av[i] * sv[j];
            }
        }
    }
    if (active) {
        #pragma unroll
        for (int i = 0; i < 4; i++)
            #pragma unroll
            for (int j = 0; j < 6; j++)
                g_ast[(((size_t)b*H_ + h0 + i)*S_ + q0 + qq)*SD_ + c0 + j] = acc[i][j];
    }
}

// ============================================================
// merge: g_ctx[b,s,h*64+d] = ctxa + ast@Wsv + bsv   (BETA=1, sum(attn)=1)
// ============================================================
__global__ void ctx2_kernel(const float* __restrict__ Wsv, const float* __restrict__ bsv)
{
    int idx = blockIdx.x * 256 + threadIdx.x;   // over B*H*S*DH
    if (idx >= B_*H_*S_*DH_) return;
    int d = idx & 63, row = idx >> 6;
    float acc = g_ctxa[idx] + bsv[d];
    const float* a = g_ast + (size_t)row * SD_;
    #pragma unroll
    for (int c = 0; c < SD_; c++) acc += a[c] * Wsv[c*DH_ + d];
    int s = row % S_, h = (row / S_) % H_, b = row / (S_ * H_);
    g_ctx[((size_t)b*S_ + s)*D_ + h*DH_ + d] = acc;
}

// ============================================================
extern "C" void kernel_launch(void* const* d_in, const int* in_sizes, int n_in,
                              void* d_out, int out_size)
{
    const float* key       = (const float*)d_in[0];
    const float* value     = (const float*)d_in[1];
    const float* query     = (const float*)d_in[2];
    const float* structure = (const float*)d_in[3];
    const unsigned int* mask = (const unsigned int*)d_in[4];
    const float* Wq  = (const float*)d_in[5];
    const float* bq  = (const float*)d_in[6];
    const float* Wk  = (const float*)d_in[7];
    const float* bk  = (const float*)d_in[8];
    const float* Wv  = (const float*)d_in[9];
    const float* bv  = (const float*)d_in[10];
    const float* Wsk = (const float*)d_in[11];
    const float* bsk = (const float*)d_in[12];
    const float* Wsv = (const float*)d_in[13];
    const float* bsv = (const float*)d_in[14];
    const float* Wo  = (const float*)d_in[15];
    const float* bo  = (const float*)d_in[16];
    float* out = (float*)d_out;

    dim3 gproj(12, 32);   // N/64, M/64
    gemm_kernel<<<gproj, 256>>>(query, Wq, bq, nullptr, 0.125f, 0);  // q (scaled)
    gemm_kernel<<<gproj, 256>>>(key,   Wk, bk, nullptr, 1.0f,   1);  // k
    gemm_kernel<<<gproj, 256>>>(value, Wv, bv, nullptr, 1.0f,   2);  // v
    qws_kernel<<<3072, 256>>>(Wsk, bsk);
    struct_score_kernel<<<dim3(4, 512, 4), 128>>>(structure);
    qk_gemm_kernel<<<dim3(8, 8, 48), 256>>>(mask);
    softmax_kernel<<<B_*H_*S_, 128>>>(out + (size_t)B_*S_*D_);
    av_gemm_kernel<<<dim3(8, 48), 256>>>();
    ast_kernel<<<dim3(64, 4), 128>>>(structure);
    ctx2_kernel<<<6144, 256>>>(Wsv, bsv);
    gemm_kernel<<<gproj, 256>>>(nullptr, Wo, bo, out, 1.0f, 3);      // final proj
}

// round 3
// speedup vs baseline: 1.3625x; 1.3625x over previous
#include <cuda_runtime.h>
#include <math.h>

#define B_  4
#define S_  512
#define D_  768
#define H_  12
#define DH_ 64
#define SD_ 30
#define BS_ (B_*S_)   // 2048

// ---- scratch ----
__device__ float g_q  [B_*H_*S_*DH_];
__device__ float g_k  [B_*H_*S_*DH_];
__device__ float g_v  [B_*H_*S_*DH_];
__device__ float g_qws[B_*H_*S_*SD_];
__device__ float g_qb [B_*H_*S_];
__device__ float g_attn[(size_t)B_*H_*S_*S_];
__device__ float g_ctxa[B_*H_*S_*DH_];
__device__ float g_ast [B_*H_*S_*SD_];
__device__ float g_ctx [BS_*D_];

// packed f32x2 helpers
__device__ __forceinline__ unsigned long long pack2(float x) {
    unsigned long long r;
    asm("mov.b64 %0, {%1, %1};" : "=l"(r) : "r"(__float_as_int(x)));
    return r;
}
__device__ __forceinline__ void fma2(unsigned long long& c, unsigned long long a, unsigned long long b) {
    asm("fma.rn.f32x2 %0, %1, %2, %0;" : "+l"(c) : "l"(a), "l"(b));
}
__device__ __forceinline__ void unpack2(unsigned long long v, float& lo, float& hi) {
    int a, b;
    asm("mov.b64 {%0, %1}, %2;" : "=r"(a), "=r"(b) : "l"(v));
    lo = __int_as_float(a); hi = __int_as_float(b);
}

// ============================================================
// 128x128-tile GEMM, 8x8 microtile, f32x2 FMA. M=2048,N=768,K=768.
// MODE 0: blockIdx.z selects q/k/v projection (scatter to (b,h,s,d)).
// MODE 1: X=g_ctx, plain output to extout.
// ============================================================
template<int MODE>
__global__ void __launch_bounds__(256) gemm128(
    const float* __restrict__ Aq, const float* __restrict__ Ak, const float* __restrict__ Av,
    const float* __restrict__ Wqp, const float* __restrict__ Wkp, const float* __restrict__ Wvp,
    const float* __restrict__ bqp, const float* __restrict__ bkp, const float* __restrict__ bvp,
    float* __restrict__ extout)
{
    __shared__ float As[16][132];   // k-major (transposed A tile)
    __shared__ float Bs[16][132];

    const int z = blockIdx.z;
    const float* X; const float* W; const float* bias; float scale = 1.0f;
    if (MODE == 0) {
        X    = (z == 0) ? Aq  : (z == 1) ? Ak  : Av;
        W    = (z == 0) ? Wqp : (z == 1) ? Wkp : Wvp;
        bias = (z == 0) ? bqp : (z == 1) ? bkp : bvp;
        if (z == 0) scale = 0.125f;
    } else {
        X = g_ctx; W = Wqp; bias = bqp;
    }

    const int t  = threadIdx.x;
    const int m0 = blockIdx.y * 128, n0 = blockIdx.x * 128;
    const int tx = t & 15, ty = t >> 4;
    const int lar = t >> 1;          // A row 0..127
    const int lak = (t & 1) * 8;     // A k-offset
    const int br  = t >> 5;          // B row 0..7
    const int bc4 = (t & 31) * 4;    // B col

    unsigned long long acc[8][4];
    #pragma unroll
    for (int i = 0; i < 8; i++)
        #pragma unroll
        for (int j = 0; j < 4; j++) acc[i][j] = 0ULL;

    for (int k0 = 0; k0 < 768; k0 += 16) {
        const float* xrow = X + (size_t)(m0 + lar) * 768 + k0 + lak;
        float4 a0 = *(const float4*)(xrow);
        float4 a1 = *(const float4*)(xrow + 4);
        float4 b0 = *(const float4*)(W + (size_t)(k0 + br) * 768 + n0 + bc4);
        float4 b1 = *(const float4*)(W + (size_t)(k0 + 8 + br) * 768 + n0 + bc4);
        __syncthreads();
        As[lak+0][lar] = a0.x; As[lak+1][lar] = a0.y;
        As[lak+2][lar] = a0.z; As[lak+3][lar] = a0.w;
        As[lak+4][lar] = a1.x; As[lak+5][lar] = a1.y;
        As[lak+6][lar] = a1.z; As[lak+7][lar] = a1.w;
        *(float4*)&Bs[br][bc4]     = b0;
        *(float4*)&Bs[8 + br][bc4] = b1;
        __syncthreads();
        #pragma unroll
        for (int kk = 0; kk < 16; kk++) {
            float4 af0 = *(const float4*)&As[kk][ty*4];
            float4 af1 = *(const float4*)&As[kk][64 + ty*4];
            ulonglong2 bv0 = *(const ulonglong2*)&Bs[kk][tx*4];
            ulonglong2 bv1 = *(const ulonglong2*)&Bs[kk][64 + tx*4];
            unsigned long long ar[8];
            ar[0] = pack2(af0.x); ar[1] = pack2(af0.y);
            ar[2] = pack2(af0.z); ar[3] = pack2(af0.w);
            ar[4] = pack2(af1.x); ar[5] = pack2(af1.y);
            ar[6] = pack2(af1.z); ar[7] = pack2(af1.w);
            #pragma unroll
            for (int i = 0; i < 8; i++) {
                fma2(acc[i][0], ar[i], bv0.x);
                fma2(acc[i][1], ar[i], bv0.y);
                fma2(acc[i][2], ar[i], bv1.x);
                fma2(acc[i][3], ar[i], bv1.y);
            }
        }
    }

    float* outp = extout;
    if (MODE == 0) outp = (z == 0) ? g_q : (z == 1) ? g_k : g_v;

    #pragma unroll
    for (int i = 0; i < 8; i++) {
        int mloc = (i < 4) ? (ty*4 + i) : (64 + ty*4 + i - 4);
        int m = m0 + mloc;
        #pragma unroll
        for (int jp = 0; jp < 4; jp++) {
            int nloc = (jp < 2) ? (tx*4 + jp*2) : (64 + tx*4 + (jp-2)*2);
            int n = n0 + nloc;
            float lo, hi;
            unpack2(acc[i][jp], lo, hi);
            float v0 = (lo + bias[n])   * scale;
            float v1 = (hi + bias[n+1]) * scale;
            if (MODE == 0) {
                int b_ = m >> 9, s = m & 511;
                int h0 = n >> 6, d0 = n & 63;
                int h1 = (n+1) >> 6, d1 = (n+1) & 63;
                outp[(((size_t)b_*H_ + h0)*S_ + s)*DH_ + d0] = v0;
                outp[(((size_t)b_*H_ + h1)*S_ + s)*DH_ + d1] = v1;
            } else {
                outp[(size_t)m*768 + n]     = v0;
                outp[(size_t)m*768 + n + 1] = v1;
            }
        }
    }
}

// ============================================================
// qws: smem-tiled. Block = 32 rows, 128 threads.
// thread: row = t&31, grp = t>>5 -> 8 output cols (grp3: 6 cols + qb)
// ============================================================
__global__ void __launch_bounds__(128) qws2_kernel(const float* __restrict__ Wsk,
                                                   const float* __restrict__ bsk)
{
    __shared__ float sq[32][65];
    __shared__ float sw[31][64];
    const int t = threadIdx.x;
    const int r0 = blockIdx.x * 32;

    #pragma unroll
    for (int i = 0; i < 4; i++) {          // 512 float4 of q
        int f = t + i * 128;
        int r = f >> 4, c4 = (f & 15) * 4;
        float4 v = *(const float4*)(g_q + (size_t)(r0 + r) * 64 + c4);
        sq[r][c4] = v.x; sq[r][c4+1] = v.y; sq[r][c4+2] = v.z; sq[r][c4+3] = v.w;
    }
    #pragma unroll
    for (int i = 0; i < 4; i++) {          // 496 float4 of W (30 rows Wsk + bsk)
        int f = t + i * 128;
        if (f < 496) {
            int c = f >> 4, d4 = (f & 15) * 4;
            float4 v = (c < 30) ? *(const float4*)(Wsk + c * 64 + d4)
                                : *(const float4*)(bsk + d4);
            sw[c][d4] = v.x; sw[c][d4+1] = v.y; sw[c][d4+2] = v.z; sw[c][d4+3] = v.w;
        }
    }
    __syncthreads();

    const int row = t & 31;
    const int grp = t >> 5;
    const int c0 = grp * 8;
    const int ncols = (grp < 3) ? 8 : 7;   // grp3: cols 24..29 + bsk dot
    float acc[8] = {};
    #pragma unroll
    for (int d = 0; d < 64; d++) {
        float qv = sq[row][d];
        #pragma unroll
        for (int j = 0; j < 8; j++) {
            int c = c0 + j;
            if (j < 7 || grp < 3) {
                float w = (c < 30) ? sw[c][d] : sw[30][d];
                acc[j] += qv * w;
            }
        }
    }
    int rg = r0 + row;
    if (grp < 3) {
        #pragma unroll
        for (int j = 0; j < 8; j++) g_qws[(size_t)rg*SD_ + c0 + j] = acc[j];
    } else {
        #pragma unroll
        for (int j = 0; j < 6; j++) g_qws[(size_t)rg*SD_ + 24 + j] = acc[j];
        g_qb[rg] = acc[6];
    }
    (void)ncols;
}

// ============================================================
// struct scores: g_attn[b,h,q,k] = structure[b,q,k,:] . qws[b,h,q,:] + qb
// ============================================================
__global__ void struct_score_kernel(const float* __restrict__ structure)
{
    int b = blockIdx.z, q = blockIdx.y;
    int k = blockIdx.x * 128 + threadIdx.x;
    __shared__ float qw[H_][SD_];
    __shared__ float qb[H_];
    int t = threadIdx.x;
    for (int i = t; i < H_*SD_; i += 128) {
        int h = i / SD_, c = i % SD_;
        qw[h][c] = g_qws[(((size_t)b*H_ + h)*S_ + q)*SD_ + c];
    }
    if (t < H_) qb[t] = g_qb[((size_t)b*H_ + t)*S_ + q];
    __syncthreads();

    const float* st = structure + ((size_t)(b*S_ + q)*S_ + k) * SD_;
    float sv[SD_];
    #pragma unroll
    for (int c = 0; c < SD_; c += 2) {
        float2 v = *(const float2*)(st + c);
        sv[c] = v.x; sv[c+1] = v.y;
    }
    #pragma unroll
    for (int h = 0; h < H_; h++) {
        float acc = qb[h];
        #pragma unroll
        for (int c = 0; c < SD_; c++) acc += sv[c] * qw[h][c];
        g_attn[(((size_t)b*H_ + h)*S_ + q)*S_ + k] = acc;
    }
}

// ============================================================
// Fused QK^T + struct-score add + mask + softmax (+ top_attn for h=0).
// Block: (b,h) x 32 q-rows. Warp w owns q rows w*4..+4; lane l owns
// k = l + 32*j (j<16). Scores live in registers.
// ============================================================
__global__ void __launch_bounds__(256) attn_kernel(const unsigned int* __restrict__ mask,
                                                   float* __restrict__ top_out)
{
    const int bh = blockIdx.y;
    const int b  = bh / H_;
    const int h  = bh % H_;
    const int q0 = blockIdx.x * 32;
    const float* Q = g_q + (size_t)bh * S_ * DH_;
    const float* K = g_k + (size_t)bh * S_ * DH_;

    __shared__ float sQ[32][65];
    __shared__ float sK[16][520];

    const int t = threadIdx.x;
    const int w = t >> 5, l = t & 31;

    #pragma unroll
    for (int i = 0; i < 2; i++) {          // 512 float4 of Q tile
        int f = t + i * 256;
        int r = f >> 4, c4 = (f & 15) * 4;
        float4 v = *(const float4*)(Q + (size_t)(q0 + r) * 64 + c4);
        sQ[r][c4] = v.x; sQ[r][c4+1] = v.y; sQ[r][c4+2] = v.z; sQ[r][c4+3] = v.w;
    }

    float acc[4][16];
    #pragma unroll
    for (int i = 0; i < 4; i++)
        #pragma unroll
        for (int j = 0; j < 16; j++) acc[i][j] = 0.f;

    for (int dt = 0; dt < 4; dt++) {
        int d0 = dt * 16;
        __syncthreads();
        #pragma unroll
        for (int i = 0; i < 8; i++) {      // 2048 float4: K[k][d0..+16] -> sK[dd][k]
            int f = t + i * 256;
            int k = f >> 2, g = f & 3;
            float4 v = *(const float4*)(K + (size_t)k * 64 + d0 + g * 4);
            sK[g*4+0][k] = v.x; sK[g*4+1][k] = v.y;
            sK[g*4+2][k] = v.z; sK[g*4+3][k] = v.w;
        }
        __syncthreads();
        #pragma unroll
        for (int dd = 0; dd < 16; dd++) {
            float qv[4];
            #pragma unroll
            for (int i = 0; i < 4; i++) qv[i] = sQ[w*4 + i][d0 + dd];
            float kv[16];
            #pragma unroll
            for (int j = 0; j < 16; j++) kv[j] = sK[dd][l + 32*j];
            #pragma unroll
            for (int i = 0; i < 4; i++)
                #pragma unroll
                for (int j = 0; j < 16; j++)
                    acc[i][j] += qv[i] * kv[j];
        }
    }

    // epilogue: + struct score, mask, softmax
    #pragma unroll
    for (int i = 0; i < 4; i++) {
        int q = q0 + w*4 + i;
        size_t arow = ((size_t)bh * S_ + q) * S_;
        size_t mrow = ((size_t)b  * S_ + q) * S_;
        float mx = -3.0e38f;
        #pragma unroll
        for (int j = 0; j < 16; j++) {
            int k = l + 32*j;
            float v = acc[i][j] + g_attn[arow + k];
            if (mask[mrow + k] != 0u) v = -1e18f;
            acc[i][j] = v;
            mx = fmaxf(mx, v);
        }
        #pragma unroll
        for (int o = 16; o > 0; o >>= 1) mx = fmaxf(mx, __shfl_xor_sync(0xffffffffu, mx, o));
        float s = 0.f;
        #pragma unroll
        for (int j = 0; j < 16; j++) {
            float e = __expf(acc[i][j] - mx);
            acc[i][j] = e;
            s += e;
        }
        #pragma unroll
        for (int o = 16; o > 0; o >>= 1) s += __shfl_xor_sync(0xffffffffu, s, o);
        float inv = 1.0f / s;
        #pragma unroll
        for (int j = 0; j < 16; j++) {
            float e = acc[i][j] * inv;
            g_attn[arow + l + 32*j] = e;
            if (h == 0) top_out[mrow + l + 32*j] = e;
        }
    }
}

// ============================================================
// attn @ V per (b,h) -> g_ctxa  (f32x2 inner loop)
// ============================================================
__global__ void __launch_bounds__(256) av_gemm_kernel()
{
    int bh = blockIdx.y;
    const float* A = g_attn + (size_t)bh * S_ * S_;
    const float* V = g_v    + (size_t)bh * S_ * DH_;
    int q0 = blockIdx.x * 64;
    __shared__ float As[16][68], Vs[16][68];
    int t = threadIdx.x;
    int tx = t & 15, ty = t >> 4;
    int lr = t >> 2, lc4 = (t & 3) * 4;
    int bk = t >> 4, bn4 = (t & 15) * 4;
    unsigned long long acc[4][2];
    #pragma unroll
    for (int i = 0; i < 4; i++) { acc[i][0] = 0ULL; acc[i][1] = 0ULL; }

    for (int k0 = 0; k0 < 512; k0 += 16) {
        float4 a = *(const float4*)(A + (size_t)(q0 + lr)*512 + k0 + lc4);
        float4 b = *(const float4*)(V + (size_t)(k0 + bk)*64 + bn4);
        __syncthreads();
        As[lc4+0][lr]=a.x; As[lc4+1][lr]=a.y; As[lc4+2][lr]=a.z; As[lc4+3][lr]=a.w;
        *(float4*)&Vs[bk][bn4] = b;
        __syncthreads();
        #pragma unroll
        for (int kk = 0; kk < 16; kk++) {
            float4 af = *(const float4*)&As[kk][ty*4];
            ulonglong2 bv = *(const ulonglong2*)&Vs[kk][tx*4];
            unsigned long long ar[4];
            ar[0] = pack2(af.x); ar[1] = pack2(af.y);
            ar[2] = pack2(af.z); ar[3] = pack2(af.w);
            #pragma unroll
            for (int i = 0; i < 4; i++) {
                fma2(acc[i][0], ar[i], bv.x);
                fma2(acc[i][1], ar[i], bv.y);
            }
        }
    }
    #pragma unroll
    for (int i = 0; i < 4; i++) {
        float lo, hi;
        size_t base = ((size_t)bh*S_ + q0 + ty*4 + i)*DH_ + tx*4;
        unpack2(acc[i][0], lo, hi);
        g_ctxa[base + 0] = lo; g_ctxa[base + 1] = hi;
        unpack2(acc[i][1], lo, hi);
        g_ctxa[base + 2] = lo; g_ctxa[base + 3] = hi;
    }
}

// ============================================================
// g_ast[b,h,q,c] = sum_k attn[b,h,q,k] * structure[b,q,k,c]
// ============================================================
__global__ void ast_kernel(const float* __restrict__ structure)
{
    int b = blockIdx.y, q0 = blockIdx.x * 8;
    __shared__ float sA[8][12][33];
    __shared__ float sS[32][8][33];
    int t = threadIdx.x;
    bool active = t < 120;
    int qq = 0, h0 = 0, c0 = 0;
    if (active) { qq = t / 15; int g = t % 15; h0 = (g / 5) * 4; c0 = (g % 5) * 6; }
    float acc[4][6] = {};

    for (int k0 = 0; k0 < 512; k0 += 32) {
        __syncthreads();
        for (int i = t; i < 8*12*32; i += 128) {
            int iq = i / 384; int r = i % 384; int ih = r >> 5; int ik = r & 31;
            sA[iq][ih][ik] = g_attn[(((size_t)b*H_ + ih)*S_ + q0 + iq)*S_ + k0 + ik];
        }
        for (int i = t; i < 8*32*30; i += 128) {
            int iq = i / 960; int r = i % 960; int ik = r / 30; int c = r % 30;
            sS[ik][iq][c] = structure[((size_t)(b*S_ + q0 + iq)*S_ + k0 + ik)*SD_ + c];
        }
        __syncthreads();
        if (active) {
            #pragma unroll 4
            for (int kk = 0; kk < 32; kk++) {
                float av[4], sv[6];
                #pragma unroll
                for (int i = 0; i < 4; i++) av[i] = sA[qq][h0 + i][kk];
                #pragma unroll
                for (int j = 0; j < 6; j++) sv[j] = sS[kk][qq][c0 + j];
                #pragma unroll
                for (int i = 0; i < 4; i++)
                    #pragma unroll
                    for (int j = 0; j < 6; j++)
                        acc[i][j] += av[i] * sv[j];
            }
        }
    }
    if (active) {
        #pragma unroll
        for (int i = 0; i < 4; i++)
            #pragma unroll
            for (int j = 0; j < 6; j++)
                g_ast[(((size_t)b*H_ + h0 + i)*S_ + q0 + qq)*SD_ + c0 + j] = acc[i][j];
    }
}

// ============================================================
// merge: g_ctx = ctxa + ast@Wsv + bsv
// ============================================================
__global__ void ctx2_kernel(const float* __restrict__ Wsv, const float* __restrict__ bsv)
{
    int idx = blockIdx.x * 256 + threadIdx.x;
    if (idx >= B_*H_*S_*DH_) return;
    int d = idx & 63, row = idx >> 6;
    float acc = g_ctxa[idx] + bsv[d];
    const float* a = g_ast + (size_t)row * SD_;
    #pragma unroll
    for (int c = 0; c < SD_; c++) acc += a[c] * Wsv[c*DH_ + d];
    int s = row % S_, h = (row / S_) % H_, b = row / (S_ * H_);
    g_ctx[((size_t)b*S_ + s)*D_ + h*DH_ + d] = acc;
}

// ============================================================
extern "C" void kernel_launch(void* const* d_in, const int* in_sizes, int n_in,
                              void* d_out, int out_size)
{
    const float* key       = (const float*)d_in[0];
    const float* value     = (const float*)d_in[1];
    const float* query     = (const float*)d_in[2];
    const float* structure = (const float*)d_in[3];
    const unsigned int* mask = (const unsigned int*)d_in[4];
    const float* Wq  = (const float*)d_in[5];
    const float* bq  = (const float*)d_in[6];
    const float* Wk  = (const float*)d_in[7];
    const float* bk  = (const float*)d_in[8];
    const float* Wv  = (const float*)d_in[9];
    const float* bv  = (const float*)d_in[10];
    const float* Wsk = (const float*)d_in[11];
    const float* bsk = (const float*)d_in[12];
    const float* Wsv = (const float*)d_in[13];
    const float* bsv = (const float*)d_in[14];
    const float* Wo  = (const float*)d_in[15];
    const float* bo  = (const float*)d_in[16];
    float* out = (float*)d_out;

    gemm128<0><<<dim3(6, 16, 3), 256>>>(query, key, value, Wq, Wk, Wv, bq, bk, bv, nullptr);
    qws2_kernel<<<768, 128>>>(Wsk, bsk);
    struct_score_kernel<<<dim3(4, 512, 4), 128>>>(structure);
    attn_kernel<<<dim3(16, 48), 256>>>(mask, out + (size_t)B_*S_*D_);
    av_gemm_kernel<<<dim3(8, 48), 256>>>();
    ast_kernel<<<dim3(64, 4), 128>>>(structure);
    ctx2_kernel<<<6144, 256>>>(Wsv, bsv);
    gemm128<1><<<dim3(6, 16, 1), 256>>>(nullptr, nullptr, nullptr, Wo, nullptr, nullptr,
                                        bo, nullptr, nullptr, out);
}

// round 5
// speedup vs baseline: 1.4438x; 1.0597x over previous
#include <cuda_runtime.h>
#include <cuda_bf16.h>
#include <stdint.h>
#include <math.h>

#define B_  4
#define S_  512
#define D_  768
#define H_  12
#define DH_ 64
#define SD_ 30
#define BS_ (B_*S_)   // 2048

// ---- scratch ----
__device__ float g_q  [B_*H_*S_*DH_];
__device__ float g_k  [B_*H_*S_*DH_];
__device__ float g_v  [B_*H_*S_*DH_];
__device__ float g_qws[B_*H_*S_*SD_];
__device__ float g_qb [B_*H_*S_];
__device__ float g_attn[(size_t)B_*H_*S_*S_];
__device__ float g_ctxa[B_*H_*S_*DH_];
__device__ float g_ast [B_*H_*S_*SD_];
__device__ float g_ctx [BS_*D_];

// ================= f32x2 helpers =================
__device__ __forceinline__ unsigned long long pack2(float x) {
    unsigned long long r;
    asm("mov.b64 %0, {%1, %1};" : "=l"(r) : "r"(__float_as_int(x)));
    return r;
}
__device__ __forceinline__ void fma2(unsigned long long& c, unsigned long long a, unsigned long long b) {
    asm("fma.rn.f32x2 %0, %1, %2, %0;" : "+l"(c) : "l"(a), "l"(b));
}
__device__ __forceinline__ void unpack2(unsigned long long v, float& lo, float& hi) {
    int a, b;
    asm("mov.b64 {%0, %1}, %2;" : "=r"(a), "=r"(b) : "l"(v));
    lo = __int_as_float(a); hi = __int_as_float(b);
}

// ================= HMMA helper =================
__device__ __forceinline__ void mma_bf16(float* c, const uint32_t* a, const uint32_t* b) {
    asm volatile("mma.sync.aligned.m16n8k16.row.col.f32.bf16.bf16.f32 "
        "{%0,%1,%2,%3}, {%4,%5,%6,%7}, {%8,%9}, {%0,%1,%2,%3};"
        : "+f"(c[0]), "+f"(c[1]), "+f"(c[2]), "+f"(c[3])
        : "r"(a[0]), "r"(a[1]), "r"(a[2]), "r"(a[3]), "r"(b[0]), "r"(b[1]));
}
__device__ __forceinline__ void split_bf16(float x, __nv_bfloat16& h, __nv_bfloat16& l) {
    h = __float2bfloat16(x);
    l = __float2bfloat16(x - __bfloat162float(h));
}

// ============================================================
// HMMA bf16-split GEMM: C[m0..+128, n0..+64] = X @ W + bias (*scale)
// 3-term split: D = Ah*Bh + Ah*Bl + Al*Bh (fp32 accum).
// MODE 0: z selects q/k/v projection (scatter to (b,h,s,d)).
// MODE 1: X = g_ctx, plain output to extout.
// ============================================================
template<int MODE>
__global__ void __launch_bounds__(256) gemm_mma(
    const float* __restrict__ Aq, const float* __restrict__ Ak, const float* __restrict__ Av,
    const float* __restrict__ Wq_, const float* __restrict__ Wk_, const float* __restrict__ Wv_,
    const float* __restrict__ bq_, const float* __restrict__ bk_, const float* __restrict__ bv_,
    float* __restrict__ extout)
{
    __shared__ __nv_bfloat16 sAh[128][40];
    __shared__ __nv_bfloat16 sAl[128][40];
    __shared__ __nv_bfloat16 sBh[64][40];    // transposed: [n][k]
    __shared__ __nv_bfloat16 sBl[64][40];

    const int t = threadIdx.x;
    const int z = blockIdx.z;

    const float* X; const float* W; const float* bias; float scale = 1.0f;
    if (MODE == 0) {
        X    = (z == 0) ? Aq  : (z == 1) ? Ak  : Av;
        W    = (z == 0) ? Wq_ : (z == 1) ? Wk_ : Wv_;
        bias = (z == 0) ? bq_ : (z == 1) ? bk_ : bv_;
        if (z == 0) scale = 0.125f;
    } else {
        X = g_ctx; W = Wq_; bias = bq_;
    }
    const int m0 = blockIdx.y * 128, n0 = blockIdx.x * 64;
    const int w = t >> 5, l = t & 31;
    const int wm = (w >> 1) * 32, wn = (w & 1) * 32;
    const int lq = l >> 2, lr = l & 3;       // quad row / pair col

    float C[2][4][4];
    #pragma unroll
    for (int i = 0; i < 2; i++)
        #pragma unroll
        for (int j = 0; j < 4; j++)
            #pragma unroll
            for (int p = 0; p < 4; p++) C[i][j][p] = 0.f;

    for (int k0 = 0; k0 < 768; k0 += 32) {
        __syncthreads();
        // stage A: 128x32 fp32 -> hi/lo bf16
        #pragma unroll
        for (int it = 0; it < 4; it++) {
            int f = t + it * 256;
            int m = f >> 3, k4 = (f & 7) * 4;
            float4 v = *(const float4*)(X + (size_t)(m0 + m) * 768 + k0 + k4);
            __nv_bfloat16 h0,h1,h2,h3, l0,l1,l2,l3;
            split_bf16(v.x, h0, l0); split_bf16(v.y, h1, l1);
            split_bf16(v.z, h2, l2); split_bf16(v.w, h3, l3);
            uint32_t hA = (uint32_t)__bfloat16_as_ushort(h0) | ((uint32_t)__bfloat16_as_ushort(h1) << 16);
            uint32_t hB = (uint32_t)__bfloat16_as_ushort(h2) | ((uint32_t)__bfloat16_as_ushort(h3) << 16);
            uint32_t lA = (uint32_t)__bfloat16_as_ushort(l0) | ((uint32_t)__bfloat16_as_ushort(l1) << 16);
            uint32_t lB = (uint32_t)__bfloat16_as_ushort(l2) | ((uint32_t)__bfloat16_as_ushort(l3) << 16);
            *(uint2*)&sAh[m][k4] = make_uint2(hA, hB);
            *(uint2*)&sAl[m][k4] = make_uint2(lA, lB);
        }
        // stage B (W chunk [32][64]) transposed to [n][k]
        #pragma unroll
        for (int it = 0; it < 2; it++) {
            int f = t + it * 256;
            int kk = f >> 4, n4 = (f & 15) * 4;
            float4 v = *(const float4*)(W + (size_t)(k0 + kk) * 768 + n0 + n4);
            __nv_bfloat16 h, lo;
            split_bf16(v.x, h, lo); sBh[n4+0][kk] = h; sBl[n4+0][kk] = lo;
            split_bf16(v.y, h, lo); sBh[n4+1][kk] = h; sBl[n4+1][kk] = lo;
            split_bf16(v.z, h, lo); sBh[n4+2][kk] = h; sBl[n4+2][kk] = lo;
            split_bf16(v.w, h, lo); sBh[n4+3][kk] = h; sBl[n4+3][kk] = lo;
        }
        __syncthreads();

        #pragma unroll
        for (int s = 0; s < 2; s++) {
            const int kc = s * 16 + lr * 2;
            uint32_t ah[2][4], al[2][4];
            #pragma unroll
            for (int i = 0; i < 2; i++) {
                int r = wm + i * 16 + lq;
                ah[i][0] = *(const uint32_t*)&sAh[r][kc];
                ah[i][1] = *(const uint32_t*)&sAh[r + 8][kc];
                ah[i][2] = *(const uint32_t*)&sAh[r][kc + 8];
                ah[i][3] = *(const uint32_t*)&sAh[r + 8][kc + 8];
                al[i][0] = *(const uint32_t*)&sAl[r][kc];
                al[i][1] = *(const uint32_t*)&sAl[r + 8][kc];
                al[i][2] = *(const uint32_t*)&sAl[r][kc + 8];
                al[i][3] = *(const uint32_t*)&sAl[r + 8][kc + 8];
            }
            uint32_t bh[4][2], bl[4][2];
            #pragma unroll
            for (int j = 0; j < 4; j++) {
                int n = wn + j * 8 + lq;
                bh[j][0] = *(const uint32_t*)&sBh[n][kc];
                bh[j][1] = *(const uint32_t*)&sBh[n][kc + 8];
                bl[j][0] = *(const uint32_t*)&sBl[n][kc];
                bl[j][1] = *(const uint32_t*)&sBl[n][kc + 8];
            }
            #pragma unroll
            for (int i = 0; i < 2; i++)
                #pragma unroll
                for (int j = 0; j < 4; j++) {
                    mma_bf16(C[i][j], ah[i], bh[j]);
                    mma_bf16(C[i][j], ah[i], bl[j]);
                    mma_bf16(C[i][j], al[i], bh[j]);
                }
        }
    }

    // epilogue
    #pragma unroll
    for (int i = 0; i < 2; i++) {
        #pragma unroll
        for (int j = 0; j < 4; j++) {
            int rA = m0 + wm + i * 16 + lq;
            int cA = n0 + wn + j * 8 + lr * 2;
            #pragma unroll
            for (int half = 0; half < 2; half++) {
                int m = rA + half * 8;
                float v0 = (C[i][j][half*2 + 0] + bias[cA])     * scale;
                float v1 = (C[i][j][half*2 + 1] + bias[cA + 1]) * scale;
                if (MODE == 0) {
                    int b_ = m >> 9, s = m & 511, h = cA >> 6, d = cA & 63;
                    float* op = ((z == 0) ? g_q : (z == 1) ? g_k : g_v)
                              + (((size_t)b_ * H_ + h) * S_ + s) * DH_ + d;
                    *(float2*)op = make_float2(v0, v1);
                } else {
                    *(float2*)(extout + (size_t)m * 768 + cA) = make_float2(v0, v1);
                }
            }
        }
    }
}

// ============================================================
// qws: smem-tiled. Block = 32 rows, 128 threads.
// ============================================================
__global__ void __launch_bounds__(128) qws2_kernel(const float* __restrict__ Wsk,
                                                   const float* __restrict__ bsk)
{
    __shared__ float sq[32][65];
    __shared__ float sw[31][64];
    const int t = threadIdx.x;
    const int r0 = blockIdx.x * 32;

    #pragma unroll
    for (int i = 0; i < 4; i++) {
        int f = t + i * 128;
        int r = f >> 4, c4 = (f & 15) * 4;
        float4 v = *(const float4*)(g_q + (size_t)(r0 + r) * 64 + c4);
        sq[r][c4] = v.x; sq[r][c4+1] = v.y; sq[r][c4+2] = v.z; sq[r][c4+3] = v.w;
    }
    #pragma unroll
    for (int i = 0; i < 4; i++) {
        int f = t + i * 128;
        if (f < 496) {
            int c = f >> 4, d4 = (f & 15) * 4;
            float4 v = (c < 30) ? *(const float4*)(Wsk + c * 64 + d4)
                                : *(const float4*)(bsk + d4);
            sw[c][d4] = v.x; sw[c][d4+1] = v.y; sw[c][d4+2] = v.z; sw[c][d4+3] = v.w;
        }
    }
    __syncthreads();

    const int row = t & 31;
    const int grp = t >> 5;
    const int c0 = grp * 8;
    float acc[8] = {};
    #pragma unroll
    for (int d = 0; d < 64; d++) {
        float qv = sq[row][d];
        #pragma unroll
        for (int j = 0; j < 8; j++) {
            int c = c0 + j;
            if (j < 7 || grp < 3) {
                float wv = (c < 30) ? sw[c][d] : sw[30][d];
                acc[j] += qv * wv;
            }
        }
    }
    int rg = r0 + row;
    if (grp < 3) {
        #pragma unroll
        for (int j = 0; j < 8; j++) g_qws[(size_t)rg*SD_ + c0 + j] = acc[j];
    } else {
        #pragma unroll
        for (int j = 0; j < 6; j++) g_qws[(size_t)rg*SD_ + 24 + j] = acc[j];
        g_qb[rg] = acc[6];
    }
}

// ============================================================
// struct scores: g_attn[b,h,q,k] = structure[b,q,k,:] . qws[b,h,q,:] + qb
// ============================================================
__global__ void struct_score_kernel(const float* __restrict__ structure)
{
    int b = blockIdx.z, q = blockIdx.y;
    int k = blockIdx.x * 128 + threadIdx.x;
    __shared__ float qw[H_][SD_];
    __shared__ float qb[H_];
    int t = threadIdx.x;
    for (int i = t; i < H_*SD_; i += 128) {
        int h = i / SD_, c = i % SD_;
        qw[h][c] = g_qws[(((size_t)b*H_ + h)*S_ + q)*SD_ + c];
    }
    if (t < H_) qb[t] = g_qb[((size_t)b*H_ + t)*S_ + q];
    __syncthreads();

    const float* st = structure + ((size_t)(b*S_ + q)*S_ + k) * SD_;
    float sv[SD_];
    #pragma unroll
    for (int c = 0; c < SD_; c += 2) {
        float2 v = *(const float2*)(st + c);
        sv[c] = v.x; sv[c+1] = v.y;
    }
    #pragma unroll
    for (int h = 0; h < H_; h++) {
        float acc = qb[h];
        #pragma unroll
        for (int c = 0; c < SD_; c++) acc += sv[c] * qw[h][c];
        g_attn[(((size_t)b*H_ + h)*S_ + q)*S_ + k] = acc;
    }
}

// ============================================================
// Fused QK^T + struct-score add + mask + softmax (+ top_attn for h=0).
// ============================================================
__global__ void __launch_bounds__(256) attn_kernel(const unsigned int* __restrict__ mask,
                                                   float* __restrict__ top_out)
{
    const int bh = blockIdx.y;
    const int b  = bh / H_;
    const int h  = bh % H_;
    const int q0 = blockIdx.x * 32;
    const float* Q = g_q + (size_t)bh * S_ * DH_;
    const float* K = g_k + (size_t)bh * S_ * DH_;

    __shared__ float sQ[32][65];
    __shared__ float sK[16][520];

    const int t = threadIdx.x;
    const int w = t >> 5, l = t & 31;

    #pragma unroll
    for (int i = 0; i < 2; i++) {
        int f = t + i * 256;
        int r = f >> 4, c4 = (f & 15) * 4;
        float4 v = *(const float4*)(Q + (size_t)(q0 + r) * 64 + c4);
        sQ[r][c4] = v.x; sQ[r][c4+1] = v.y; sQ[r][c4+2] = v.z; sQ[r][c4+3] = v.w;
    }

    float acc[4][16];
    #pragma unroll
    for (int i = 0; i < 4; i++)
        #pragma unroll
        for (int j = 0; j < 16; j++) acc[i][j] = 0.f;

    for (int dt = 0; dt < 4; dt++) {
        int d0 = dt * 16;
        __syncthreads();
        #pragma unroll
        for (int i = 0; i < 8; i++) {
            int f = t + i * 256;
            int k = f >> 2, g = f & 3;
            float4 v = *(const float4*)(K + (size_t)k * 64 + d0 + g * 4);
            sK[g*4+0][k] = v.x; sK[g*4+1][k] = v.y;
            sK[g*4+2][k] = v.z; sK[g*4+3][k] = v.w;
        }
        __syncthreads();
        #pragma unroll
        for (int dd = 0; dd < 16; dd++) {
            float qv[4];
            #pragma unroll
            for (int i = 0; i < 4; i++) qv[i] = sQ[w*4 + i][d0 + dd];
            float kv[16];
            #pragma unroll
            for (int j = 0; j < 16; j++) kv[j] = sK[dd][l + 32*j];
            #pragma unroll
            for (int i = 0; i < 4; i++)
                #pragma unroll
                for (int j = 0; j < 16; j++)
                    acc[i][j] += qv[i] * kv[j];
        }
    }

    #pragma unroll
    for (int i = 0; i < 4; i++) {
        int q = q0 + w*4 + i;
        size_t arow = ((size_t)bh * S_ + q) * S_;
        size_t mrow = ((size_t)b  * S_ + q) * S_;
        float mx = -3.0e38f;
        #pragma unroll
        for (int j = 0; j < 16; j++) {
            int k = l + 32*j;
            float v = acc[i][j] + g_attn[arow + k];
            if (mask[mrow + k] != 0u) v = -1e18f;
            acc[i][j] = v;
            mx = fmaxf(mx, v);
        }
        #pragma unroll
        for (int o = 16; o > 0; o >>= 1) mx = fmaxf(mx, __shfl_xor_sync(0xffffffffu, mx, o));
        float s = 0.f;
        #pragma unroll
        for (int j = 0; j < 16; j++) {
            float e = __expf(acc[i][j] - mx);
            acc[i][j] = e;
            s += e;
        }
        #pragma unroll
        for (int o = 16; o > 0; o >>= 1) s += __shfl_xor_sync(0xffffffffu, s, o);
        float inv = 1.0f / s;
        #pragma unroll
        for (int j = 0; j < 16; j++) {
            float e = acc[i][j] * inv;
            g_attn[arow + l + 32*j] = e;
            if (h == 0) top_out[mrow + l + 32*j] = e;
        }
    }
}

// ============================================================
// attn @ V per (b,h) -> g_ctxa  (f32x2 inner loop)
// ============================================================
__global__ void __launch_bounds__(256) av_gemm_kernel()
{
    int bh = blockIdx.y;
    const float* A = g_attn + (size_t)bh * S_ * S_;
    const float* V = g_v    + (size_t)bh * S_ * DH_;
    int q0 = blockIdx.x * 64;
    __shared__ float As[16][68], Vs[16][68];
    int t = threadIdx.x;
    int tx = t & 15, ty = t >> 4;
    int lr = t >> 2, lc4 = (t & 3) * 4;
    int bk = t >> 4, bn4 = (t & 15) * 4;
    unsigned long long acc[4][2];
    #pragma unroll
    for (int i = 0; i < 4; i++) { acc[i][0] = 0ULL; acc[i][1] = 0ULL; }

    for (int k0 = 0; k0 < 512; k0 += 16) {
        float4 a = *(const float4*)(A + (size_t)(q0 + lr)*512 + k0 + lc4);
        float4 b = *(const float4*)(V + (size_t)(k0 + bk)*64 + bn4);
        __syncthreads();
        As[lc4+0][lr]=a.x; As[lc4+1][lr]=a.y; As[lc4+2][lr]=a.z; As[lc4+3][lr]=a.w;
        *(float4*)&Vs[bk][bn4] = b;
        __syncthreads();
        #pragma unroll
        for (int kk = 0; kk < 16; kk++) {
            float4 af = *(const float4*)&As[kk][ty*4];
            ulonglong2 bv = *(const ulonglong2*)&Vs[kk][tx*4];
            unsigned long long ar[4];
            ar[0] = pack2(af.x); ar[1] = pack2(af.y);
            ar[2] = pack2(af.z); ar[3] = pack2(af.w);
            #pragma unroll
            for (int i = 0; i < 4; i++) {
                fma2(acc[i][0], ar[i], bv.x);
                fma2(acc[i][1], ar[i], bv.y);
            }
        }
    }
    #pragma unroll
    for (int i = 0; i < 4; i++) {
        float lo, hi;
        size_t base = ((size_t)bh*S_ + q0 + ty*4 + i)*DH_ + tx*4;
        unpack2(acc[i][0], lo, hi);
        g_ctxa[base + 0] = lo; g_ctxa[base + 1] = hi;
        unpack2(acc[i][1], lo, hi);
        g_ctxa[base + 2] = lo; g_ctxa[base + 3] = hi;
    }
}

// ============================================================
// g_ast[b,h,q,c] = sum_k attn[b,h,q,k] * structure[b,q,k,c]
// ============================================================
__global__ void ast_kernel(const float* __restrict__ structure)
{
    int b = blockIdx.y, q0 = blockIdx.x * 8;
    __shared__ float sA[8][12][33];
    __shared__ float sS[32][8][33];
    int t = threadIdx.x;
    bool active = t < 120;
    int qq = 0, h0 = 0, c0 = 0;
    if (active) { qq = t / 15; int g = t % 15; h0 = (g / 5) * 4; c0 = (g % 5) * 6; }
    float acc[4][6] = {};

    for (int k0 = 0; k0 < 512; k0 += 32) {
        __syncthreads();
        for (int i = t; i < 8*12*32; i += 128) {
            int iq = i / 384; int r = i % 384; int ih = r >> 5; int ik = r & 31;
            sA[iq][ih][ik] = g_attn[(((size_t)b*H_ + ih)*S_ + q0 + iq)*S_ + k0 + ik];
        }
        for (int i = t; i < 8*32*30; i += 128) {
            int iq = i / 960; int r = i % 960; int ik = r / 30; int c = r % 30;
            sS[ik][iq][c] = structure[((size_t)(b*S_ + q0 + iq)*S_ + k0 + ik)*SD_ + c];
        }
        __syncthreads();
        if (active) {
            #pragma unroll 4
            for (int kk = 0; kk < 32; kk++) {
                float av[4], sv[6];
                #pragma unroll
                for (int i = 0; i < 4; i++) av[i] = sA[qq][h0 + i][kk];
                #pragma unroll
                for (int j = 0; j < 6; j++) sv[j] = sS[kk][qq][c0 + j];
                #pragma unroll
                for (int i = 0; i < 4; i++)
                    #pragma unroll
                    for (int j = 0; j < 6; j++)
                        acc[i][j] += av[i] * sv[j];
            }
        }
    }
    if (active) {
        #pragma unroll
        for (int i = 0; i < 4; i++)
            #pragma unroll
            for (int j = 0; j < 6; j++)
                g_ast[(((size_t)b*H_ + h0 + i)*S_ + q0 + qq)*SD_ + c0 + j] = acc[i][j];
    }
}

// ============================================================
// merge: g_ctx = ctxa + ast@Wsv + bsv
// ============================================================
__global__ void ctx2_kernel(const float* __restrict__ Wsv, const float* __restrict__ bsv)
{
    int idx = blockIdx.x * 256 + threadIdx.x;
    if (idx >= B_*H_*S_*DH_) return;
    int d = idx & 63, row = idx >> 6;
    float acc = g_ctxa[idx] + bsv[d];
    const float* a = g_ast + (size_t)row * SD_;
    #pragma unroll
    for (int c = 0; c < SD_; c++) acc += a[c] * Wsv[c*DH_ + d];
    int s = row % S_, h = (row / S_) % H_, b = row / (S_ * H_);
    g_ctx[((size_t)b*S_ + s)*D_ + h*DH_ + d] = acc;
}

// ============================================================
extern "C" void kernel_launch(void* const* d_in, const int* in_sizes, int n_in,
                              void* d_out, int out_size)
{
    const float* key       = (const float*)d_in[0];
    const float* value     = (const float*)d_in[1];
    const float* query     = (const float*)d_in[2];
    const float* structure = (const float*)d_in[3];
    const unsigned int* mask = (const unsigned int*)d_in[4];
    const float* Wq  = (const float*)d_in[5];
    const float* bq  = (const float*)d_in[6];
    const float* Wk  = (const float*)d_in[7];
    const float* bk  = (const float*)d_in[8];
    const float* Wv  = (const float*)d_in[9];
    const float* bv  = (const float*)d_in[10];
    const float* Wsk = (const float*)d_in[11];
    const float* bsk = (const float*)d_in[12];
    const float* Wsv = (const float*)d_in[13];
    const float* bsv = (const float*)d_in[14];
    const float* Wo  = (const float*)d_in[15];
    const float* bo  = (const float*)d_in[16];
    float* out = (float*)d_out;

    gemm_mma<0><<<dim3(12, 16, 3), 256>>>(query, key, value, Wq, Wk, Wv, bq, bk, bv, nullptr);
    qws2_kernel<<<768, 128>>>(Wsk, bsk);
    struct_score_kernel<<<dim3(4, 512, 4), 128>>>(structure);
    attn_kernel<<<dim3(16, 48), 256>>>(mask, out + (size_t)B_*S_*D_);
    av_gemm_kernel<<<dim3(8, 48), 256>>>();
    ast_kernel<<<dim3(64, 4), 128>>>(structure);
    ctx2_kernel<<<6144, 256>>>(Wsv, bsv);
    gemm_mma<1><<<dim3(12, 16, 1), 256>>>(nullptr, nullptr, nullptr, Wo, nullptr, nullptr,
                                          bo, nullptr, nullptr, out);
}